// round 1
// baseline (speedup 1.0000x reference)
#include <cuda_runtime.h>
#include <math_constants.h>

// Problem constants
#define BB 4
#define TT 2048
#define CC 768
#define HH 768
#define MTOT (BB * TT)          // 8192
static const float QK_SCALE = 0.03608439182435161f;  // 1/sqrt(768)

// Scratch (static device globals: allowed; no runtime allocation)
__device__ float g_q[(size_t)BB * TT * HH];
__device__ float g_k[(size_t)BB * TT * HH];
__device__ float g_v[(size_t)BB * TT * HH];
__device__ float g_s[(size_t)BB * TT * TT];   // scores, then softmax probs in place

// ---------------------------------------------------------------------------
// Classic 128x128x8 fp32 SGEMM building blocks, 256 threads, 8x8 per thread.
// All problem dims are multiples of tile dims -> no bounds checks.
// ---------------------------------------------------------------------------

// Kernel 1: QKV projection.  out = x @ W + b  for z = 0,1,2 (q,k,v)
__global__ __launch_bounds__(256) void qkv_kernel(
    const float* __restrict__ x,
    const float* __restrict__ Wq, const float* __restrict__ bq,
    const float* __restrict__ Wk, const float* __restrict__ bk,
    const float* __restrict__ Wv, const float* __restrict__ bv)
{
    const float* W; const float* bias; float* out;
    if (blockIdx.z == 0)      { W = Wq; bias = bq; out = g_q; }
    else if (blockIdx.z == 1) { W = Wk; bias = bk; out = g_k; }
    else                      { W = Wv; bias = bv; out = g_v; }

    __shared__ __align__(16) float As[8][128];
    __shared__ __align__(16) float Bs[8][128];

    const int tid  = threadIdx.x;
    const int row0 = blockIdx.y * 128;
    const int col0 = blockIdx.x * 128;

    const int arow = tid >> 1, acol = (tid & 1) * 4;   // A: 128 rows x 8 k
    const int brow = tid >> 5, bcol = (tid & 31) * 4;  // B: 8 k x 128 cols
    const int tx = tid & 15, ty = tid >> 4;

    float acc[8][8];
    #pragma unroll
    for (int i = 0; i < 8; i++)
        #pragma unroll
        for (int j = 0; j < 8; j++) acc[i][j] = 0.0f;

    for (int k0 = 0; k0 < CC; k0 += 8) {
        float4 av = *(const float4*)(x + (size_t)(row0 + arow) * CC + k0 + acol);
        As[acol + 0][arow] = av.x;
        As[acol + 1][arow] = av.y;
        As[acol + 2][arow] = av.z;
        As[acol + 3][arow] = av.w;
        *(float4*)(&Bs[brow][bcol]) =
            *(const float4*)(W + (size_t)(k0 + brow) * HH + col0 + bcol);
        __syncthreads();

        #pragma unroll
        for (int k = 0; k < 8; k++) {
            float4 a0 = *(const float4*)(&As[k][ty * 8]);
            float4 a1 = *(const float4*)(&As[k][ty * 8 + 4]);
            float4 b0 = *(const float4*)(&Bs[k][tx * 8]);
            float4 b1 = *(const float4*)(&Bs[k][tx * 8 + 4]);
            float a[8] = {a0.x,a0.y,a0.z,a0.w,a1.x,a1.y,a1.z,a1.w};
            float b[8] = {b0.x,b0.y,b0.z,b0.w,b1.x,b1.y,b1.z,b1.w};
            #pragma unroll
            for (int i = 0; i < 8; i++)
                #pragma unroll
                for (int j = 0; j < 8; j++)
                    acc[i][j] = fmaf(a[i], b[j], acc[i][j]);
        }
        __syncthreads();
    }

    #pragma unroll
    for (int i = 0; i < 8; i++) {
        const int r = row0 + ty * 8 + i;
        #pragma unroll
        for (int j = 0; j < 8; j++) {
            const int c = col0 + tx * 8 + j;
            out[(size_t)r * HH + c] = acc[i][j] + bias[c];
        }
    }
}

// Kernel 2: causal scores S[b,i,j] = scale * dot(q[b,i,:], k[b,j,:])
// NT GEMM per batch; upper-triangular tiles skipped entirely.
__global__ __launch_bounds__(256) void scores_kernel()
{
    const int bi = blockIdx.y;            // row tile
    const int bj = blockIdx.x;            // col tile
    if (bj > bi) return;                  // fully masked tile
    const int b = blockIdx.z;

    const float* q = g_q + (size_t)b * TT * HH;
    const float* kk = g_k + (size_t)b * TT * HH;
    float* S = g_s + (size_t)b * TT * TT;

    __shared__ __align__(16) float As[8][128];
    __shared__ __align__(16) float Bs[8][128];

    const int tid  = threadIdx.x;
    const int row0 = bi * 128;
    const int col0 = bj * 128;
    const int arow = tid >> 1, acol = (tid & 1) * 4;
    const int tx = tid & 15, ty = tid >> 4;

    float acc[8][8];
    #pragma unroll
    for (int i = 0; i < 8; i++)
        #pragma unroll
        for (int j = 0; j < 8; j++) acc[i][j] = 0.0f;

    for (int k0 = 0; k0 < HH; k0 += 8) {
        float4 av = *(const float4*)(q  + (size_t)(row0 + arow) * HH + k0 + acol);
        As[acol + 0][arow] = av.x;
        As[acol + 1][arow] = av.y;
        As[acol + 2][arow] = av.z;
        As[acol + 3][arow] = av.w;
        float4 bv4 = *(const float4*)(kk + (size_t)(col0 + arow) * HH + k0 + acol);
        Bs[acol + 0][arow] = bv4.x;
        Bs[acol + 1][arow] = bv4.y;
        Bs[acol + 2][arow] = bv4.z;
        Bs[acol + 3][arow] = bv4.w;
        __syncthreads();

        #pragma unroll
        for (int k = 0; k < 8; k++) {
            float4 a0 = *(const float4*)(&As[k][ty * 8]);
            float4 a1 = *(const float4*)(&As[k][ty * 8 + 4]);
            float4 b0 = *(const float4*)(&Bs[k][tx * 8]);
            float4 b1 = *(const float4*)(&Bs[k][tx * 8 + 4]);
            float a[8] = {a0.x,a0.y,a0.z,a0.w,a1.x,a1.y,a1.z,a1.w};
            float bvv[8] = {b0.x,b0.y,b0.z,b0.w,b1.x,b1.y,b1.z,b1.w};
            #pragma unroll
            for (int i = 0; i < 8; i++)
                #pragma unroll
                for (int j = 0; j < 8; j++)
                    acc[i][j] = fmaf(a[i], bvv[j], acc[i][j]);
        }
        __syncthreads();
    }

    #pragma unroll
    for (int i = 0; i < 8; i++) {
        const int r = row0 + ty * 8 + i;
        #pragma unroll
        for (int j = 0; j < 8; j++) {
            const int c = col0 + tx * 8 + j;
            S[(size_t)r * TT + c] = acc[i][j] * QK_SCALE;
        }
    }
}

// Kernel 3: row softmax over j<=i, zeros for j>i (in place on g_s)
__global__ __launch_bounds__(256) void softmax_kernel()
{
    const int row = blockIdx.x;           // 0 .. B*T-1
    const int b = row / TT;
    const int i = row % TT;
    float* S = g_s + (size_t)b * TT * TT + (size_t)i * TT;
    const int n = i + 1;

    __shared__ float red[256];
    const int tid = threadIdx.x;

    float m = -CUDART_INF_F;
    for (int j = tid; j < n; j += 256) m = fmaxf(m, S[j]);
    red[tid] = m;
    __syncthreads();
    #pragma unroll
    for (int s = 128; s > 0; s >>= 1) {
        if (tid < s) red[tid] = fmaxf(red[tid], red[tid + s]);
        __syncthreads();
    }
    m = red[0];
    __syncthreads();

    float sum = 0.0f;
    for (int j = tid; j < n; j += 256) sum += expf(S[j] - m);
    red[tid] = sum;
    __syncthreads();
    #pragma unroll
    for (int s = 128; s > 0; s >>= 1) {
        if (tid < s) red[tid] += red[tid + s];
        __syncthreads();
    }
    const float inv = 1.0f / red[0];
    __syncthreads();

    for (int j = tid; j < TT; j += 256) {
        float p = (j < n) ? expf(S[j] - m) * inv : 0.0f;
        S[j] = p;
    }
}

// Kernel 4: out[b,i,:] = P[b,i,:] @ v[b,:,:]   (k-loop truncated at row block end)
__global__ __launch_bounds__(256) void pv_kernel(float* __restrict__ out)
{
    const int b  = blockIdx.z;
    const int bi = blockIdx.y;
    const float* P = g_s + (size_t)b * TT * TT;
    const float* V = g_v + (size_t)b * TT * HH;
    float* O = out + (size_t)b * TT * HH;

    __shared__ __align__(16) float As[8][128];
    __shared__ __align__(16) float Bs[8][128];

    const int tid  = threadIdx.x;
    const int row0 = bi * 128;
    const int col0 = blockIdx.x * 128;
    const int kend = (bi + 1) * 128;      // P is zero beyond the row block

    const int arow = tid >> 1, acol = (tid & 1) * 4;
    const int brow = tid >> 5, bcol = (tid & 31) * 4;
    const int tx = tid & 15, ty = tid >> 4;

    float acc[8][8];
    #pragma unroll
    for (int i = 0; i < 8; i++)
        #pragma unroll
        for (int j = 0; j < 8; j++) acc[i][j] = 0.0f;

    for (int k0 = 0; k0 < kend; k0 += 8) {
        float4 av = *(const float4*)(P + (size_t)(row0 + arow) * TT + k0 + acol);
        As[acol + 0][arow] = av.x;
        As[acol + 1][arow] = av.y;
        As[acol + 2][arow] = av.z;
        As[acol + 3][arow] = av.w;
        *(float4*)(&Bs[brow][bcol]) =
            *(const float4*)(V + (size_t)(k0 + brow) * HH + col0 + bcol);
        __syncthreads();

        #pragma unroll
        for (int k = 0; k < 8; k++) {
            float4 a0 = *(const float4*)(&As[k][ty * 8]);
            float4 a1 = *(const float4*)(&As[k][ty * 8 + 4]);
            float4 b0 = *(const float4*)(&Bs[k][tx * 8]);
            float4 b1 = *(const float4*)(&Bs[k][tx * 8 + 4]);
            float a[8] = {a0.x,a0.y,a0.z,a0.w,a1.x,a1.y,a1.z,a1.w};
            float bvv[8] = {b0.x,b0.y,b0.z,b0.w,b1.x,b1.y,b1.z,b1.w};
            #pragma unroll
            for (int i = 0; i < 8; i++)
                #pragma unroll
                for (int j = 0; j < 8; j++)
                    acc[i][j] = fmaf(a[i], bvv[j], acc[i][j]);
        }
        __syncthreads();
    }

    #pragma unroll
    for (int i = 0; i < 8; i++) {
        const int r = row0 + ty * 8 + i;
        #pragma unroll
        for (int j = 0; j < 8; j++) {
            const int c = col0 + tx * 8 + j;
            O[(size_t)r * HH + c] = acc[i][j];
        }
    }
}

extern "C" void kernel_launch(void* const* d_in, const int* in_sizes, int n_in,
                              void* d_out, int out_size)
{
    const float* x  = (const float*)d_in[0];
    const float* Wq = (const float*)d_in[1];
    const float* bq = (const float*)d_in[2];
    const float* Wk = (const float*)d_in[3];
    const float* bk = (const float*)d_in[4];
    const float* Wv = (const float*)d_in[5];
    const float* bv = (const float*)d_in[6];
    float* out = (float*)d_out;

    // 1) QKV projection: grid (H/128, M/128, 3)
    qkv_kernel<<<dim3(HH / 128, MTOT / 128, 3), 256>>>(x, Wq, bq, Wk, bk, Wv, bv);

    // 2) causal scores: grid (T/128, T/128, B), upper tiles early-exit
    scores_kernel<<<dim3(TT / 128, TT / 128, BB), 256>>>();

    // 3) row softmax, in place
    softmax_kernel<<<dim3(BB * TT), 256>>>();

    // 4) P @ V
    pv_kernel<<<dim3(HH / 128, TT / 128, BB), 256>>>(out);
}

// round 3
// speedup vs baseline: 3.3745x; 3.3745x over previous
#include <cuda_runtime.h>
#include <math_constants.h>
#include <cstdint>

// ---------------------------------------------------------------------------
// Problem constants
// ---------------------------------------------------------------------------
#define BB 4
#define TT 2048
#define CC 768
#define HH 768
#define MTOT (BB * TT)           // 8192
static const float QK_SCALE = 0.03608439182435161f;  // 1/sqrt(768)

// ---------------------------------------------------------------------------
// Scratch globals
// ---------------------------------------------------------------------------
__device__ float g_x [(size_t)MTOT * CC];      // tf32-rounded x
__device__ float g_wt[(size_t)3 * CC * HH];    // W^T, tf32-rounded  [z][n][k]
__device__ float g_q [(size_t)MTOT * HH];      // tf32-rounded
__device__ float g_k [(size_t)MTOT * HH];      // tf32-rounded
__device__ float g_v [(size_t)MTOT * HH];
__device__ float g_vt[(size_t)BB * HH * TT];   // V^T per batch, tf32-rounded
__device__ float g_s [(size_t)BB * TT * TT];   // scores -> probs (tf32-rounded)

// ---------------------------------------------------------------------------
// GEMM config: CTA 128x128, 256 threads (8 warps 2x4), warp tile 64x32,
// K-chunk 32, 3-stage cp.async pipeline.
// Smem rows have stride 36 floats (36 % 32 == 4) -> conflict-free LDS for the
// m16n8k8 fragment patterns (bank == lane).
// ---------------------------------------------------------------------------
#define TM 128
#define TN 128
#define TK 32
#define ROWSTRIDE 36
#define STAGE_FLOATS (2 * 128 * ROWSTRIDE)             // A + B per stage
#define NSTAGE 3
#define SMEM_BYTES (NSTAGE * STAGE_FLOATS * 4)         // 110592

__device__ __forceinline__ uint32_t smem_u32(const void* p) {
    uint32_t a;
    asm("{ .reg .u64 t; cvta.to.shared.u64 t, %1; cvt.u32.u64 %0, t; }"
        : "=r"(a) : "l"(p));
    return a;
}

__device__ __forceinline__ float rn_tf32(float x) {
    uint32_t u;
    asm("cvt.rn.tf32.f32 %0, %1;" : "=r"(u) : "f"(x));
    return __uint_as_float(u);
}

__device__ __forceinline__ void cp16(uint32_t dst, const void* src) {
    asm volatile("cp.async.cg.shared.global [%0], [%1], 16;"
                 :: "r"(dst), "l"(src) : "memory");
}

__device__ __forceinline__ void mma_tf32(float c[4], const uint32_t a[4],
                                         const uint32_t b[2]) {
    asm volatile(
        "mma.sync.aligned.m16n8k8.row.col.f32.tf32.tf32.f32 "
        "{%0,%1,%2,%3}, {%4,%5,%6,%7}, {%8,%9}, {%0,%1,%2,%3};"
        : "+f"(c[0]), "+f"(c[1]), "+f"(c[2]), "+f"(c[3])
        : "r"(a[0]), "r"(a[1]), "r"(a[2]), "r"(a[3]), "r"(b[0]), "r"(b[1]));
}

// Load one K-chunk (A: 128x32, B: 128x32) into a stage via cp.async.
__device__ __forceinline__ void load_chunk(uint32_t sA, uint32_t sB,
                                           const float* Ag, int lda,
                                           const float* Bg, int ldb, int tid) {
    #pragma unroll
    for (int i = 0; i < 4; i++) {
        int idx = tid + i * 256;          // 0..1023
        int row = idx >> 3, gc = idx & 7; // 8 x 16B granules per row
        uint32_t off = (uint32_t)(row * (ROWSTRIDE * 4) + gc * 16);
        cp16(sA + off, Ag + (size_t)row * lda + gc * 4);
        cp16(sB + off, Bg + (size_t)row * ldb + gc * 4);
    }
}

// ---------------------------------------------------------------------------
// Generic 128x128 tf32 mma.sync GEMM tile:
//   C[row0+i, col0+j] = scale * sum_k A[row0+i,k] * B[col0+j,k] (+ bias[col])
// A, B, P data must already be tf32-rounded.
// ---------------------------------------------------------------------------
__device__ __forceinline__ void gemm_tile(
    const float* __restrict__ A, int lda,
    const float* __restrict__ B, int ldb,
    float* __restrict__ C, int ldc,
    int row0, int col0, int K,
    const float* __restrict__ bias, float scale, bool round_out)
{
    extern __shared__ float smf[];
    const uint32_t sbase = smem_u32(smf);

    const int tid   = threadIdx.x;
    const int warp  = tid >> 5;
    const int lane  = tid & 31;
    const int wm    = (warp & 1) * 64;   // warp m offset
    const int wn    = (warp >> 1) * 32;  // warp n offset
    const int g     = lane >> 2;         // group id 0..7
    const int t     = lane & 3;          // thread-in-group 0..3

    const float* Arow = A + (size_t)row0 * lda;
    const float* Brow = B + (size_t)col0 * ldb;
    const int NC = K / TK;

    float acc[4][4][4];
    #pragma unroll
    for (int mi = 0; mi < 4; mi++)
        #pragma unroll
        for (int ni = 0; ni < 4; ni++)
            #pragma unroll
            for (int j = 0; j < 4; j++) acc[mi][ni][j] = 0.0f;

    // Stage bases (bytes)
    uint32_t stA[NSTAGE], stB[NSTAGE];
    #pragma unroll
    for (int s = 0; s < NSTAGE; s++) {
        stA[s] = sbase + (uint32_t)(s * STAGE_FLOATS * 4);
        stB[s] = stA[s] + (uint32_t)(128 * ROWSTRIDE * 4);
    }

    // Prologue: issue loads for first NSTAGE-1 chunks
    #pragma unroll
    for (int s = 0; s < NSTAGE - 1; s++) {
        if (s < NC)
            load_chunk(stA[s], stB[s], Arow + s * TK, lda, Brow + s * TK, ldb, tid);
        asm volatile("cp.async.commit_group;" ::: "memory");
    }

    // Per-warp smem fragment base offsets (floats)
    // A pattern: row = wm + mi*16 + g (+8), col = k0 + t (+4)
    // B pattern: row = wn + ni*8 + g,        col = k0 + t (+4)
    #pragma unroll 1
    for (int c = 0; c < NC; c++) {
        asm volatile("cp.async.wait_group %0;" :: "n"(NSTAGE - 2) : "memory");
        __syncthreads();

        const int s = c % NSTAGE;
        const float* As = smf + (size_t)(stA[s] - sbase) / 4;
        const float* Bs = smf + (size_t)(stB[s] - sbase) / 4;
        const float* ab = As + (wm + g) * ROWSTRIDE + t;
        const float* bb = Bs + (wn + g) * ROWSTRIDE + t;

        #pragma unroll
        for (int ks = 0; ks < 4; ks++) {
            const int k0 = ks * 8;
            uint32_t a[4][4], b[4][2];
            #pragma unroll
            for (int mi = 0; mi < 4; mi++) {
                const float* p = ab + mi * 16 * ROWSTRIDE + k0;
                a[mi][0] = __float_as_uint(p[0]);
                a[mi][1] = __float_as_uint(p[8 * ROWSTRIDE]);
                a[mi][2] = __float_as_uint(p[4]);
                a[mi][3] = __float_as_uint(p[8 * ROWSTRIDE + 4]);
            }
            #pragma unroll
            for (int ni = 0; ni < 4; ni++) {
                const float* p = bb + ni * 8 * ROWSTRIDE + k0;
                b[ni][0] = __float_as_uint(p[0]);
                b[ni][1] = __float_as_uint(p[4]);
            }
            #pragma unroll
            for (int mi = 0; mi < 4; mi++)
                #pragma unroll
                for (int ni = 0; ni < 4; ni++)
                    mma_tf32(acc[mi][ni], a[mi], b[ni]);
        }
        __syncthreads();

        const int cn = c + NSTAGE - 1;
        if (cn < NC)
            load_chunk(stA[cn % NSTAGE], stB[cn % NSTAGE],
                       Arow + cn * TK, lda, Brow + cn * TK, ldb, tid);
        asm volatile("cp.async.commit_group;" ::: "memory");
    }

    // Epilogue
    #pragma unroll
    for (int mi = 0; mi < 4; mi++) {
        const int r0 = row0 + wm + mi * 16 + g;
        #pragma unroll
        for (int ni = 0; ni < 4; ni++) {
            const int ccol = col0 + wn + ni * 8 + 2 * t;
            float v0 = acc[mi][ni][0] * scale;
            float v1 = acc[mi][ni][1] * scale;
            float v2 = acc[mi][ni][2] * scale;
            float v3 = acc[mi][ni][3] * scale;
            if (bias) {
                float b0 = bias[ccol], b1 = bias[ccol + 1];
                v0 += b0; v1 += b1; v2 += b0; v3 += b1;
            }
            if (round_out) {
                v0 = rn_tf32(v0); v1 = rn_tf32(v1);
                v2 = rn_tf32(v2); v3 = rn_tf32(v3);
            }
            *(float2*)(C + (size_t)r0 * ldc + ccol) = make_float2(v0, v1);
            *(float2*)(C + (size_t)(r0 + 8) * ldc + ccol) = make_float2(v2, v3);
        }
    }
}

// ---------------------------------------------------------------------------
// GEMM wrappers
// ---------------------------------------------------------------------------
__global__ __launch_bounds__(256) void qkv_mma(
    const float* __restrict__ bq, const float* __restrict__ bk,
    const float* __restrict__ bv)
{
    const int z = blockIdx.z;
    const float* bias = (z == 0) ? bq : (z == 1) ? bk : bv;
    float* out = (z == 0) ? g_q : (z == 1) ? g_k : g_v;
    const float* B = g_wt + (size_t)z * CC * HH;
    gemm_tile(g_x, CC, B, CC, out, HH,
              blockIdx.y * TM, blockIdx.x * TN, CC, bias, 1.0f, true);
}

__global__ __launch_bounds__(256) void scores_mma()
{
    const int nj = blockIdx.x, mi = blockIdx.y, b = blockIdx.z;
    if (nj > mi) return;   // tile fully above diagonal
    const float* q = g_q + (size_t)b * TT * HH;
    const float* k = g_k + (size_t)b * TT * HH;
    gemm_tile(q, HH, k, HH, g_s + (size_t)b * TT * TT, TT,
              mi * TM, nj * TN, HH, nullptr, QK_SCALE, false);
}

__global__ __launch_bounds__(256) void pv_mma(float* __restrict__ out)
{
    const int nj = blockIdx.x, mi = blockIdx.y, b = blockIdx.z;
    const float* P = g_s + (size_t)b * TT * TT;
    const float* Vt = g_vt + (size_t)b * HH * TT;
    gemm_tile(P, TT, Vt, TT, out + (size_t)b * TT * HH, HH,
              mi * TM, nj * TN, (mi + 1) * TM, nullptr, 1.0f, false);
}

// ---------------------------------------------------------------------------
// Elementwise tf32 rounding of x
// ---------------------------------------------------------------------------
__global__ __launch_bounds__(256) void round_x_kernel(const float* __restrict__ x)
{
    size_t i = (size_t)blockIdx.x * 256 + threadIdx.x;
    float4 v = ((const float4*)x)[i];
    v.x = rn_tf32(v.x); v.y = rn_tf32(v.y);
    v.z = rn_tf32(v.z); v.w = rn_tf32(v.w);
    ((float4*)g_x)[i] = v;
}

// ---------------------------------------------------------------------------
// Tiled transpose with tf32 rounding: dst[c][r] = rn(src[r][c])
// ---------------------------------------------------------------------------
__device__ __forceinline__ void transpose_tile(const float* __restrict__ src,
                                               float* __restrict__ dst,
                                               int R, int C)
{
    __shared__ float t[32][33];
    const int c0 = blockIdx.x * 32, r0 = blockIdx.y * 32;
    const int tx = threadIdx.x, ty = threadIdx.y;  // 32 x 8
    #pragma unroll
    for (int i = 0; i < 4; i++)
        t[ty + 8 * i][tx] = src[(size_t)(r0 + ty + 8 * i) * C + c0 + tx];
    __syncthreads();
    #pragma unroll
    for (int i = 0; i < 4; i++)
        dst[(size_t)(c0 + ty + 8 * i) * R + r0 + tx] = rn_tf32(t[tx][ty + 8 * i]);
}

__global__ void transpose_w_kernel(const float* __restrict__ Wq,
                                   const float* __restrict__ Wk,
                                   const float* __restrict__ Wv)
{
    const int z = blockIdx.z;
    const float* src = (z == 0) ? Wq : (z == 1) ? Wk : Wv;
    transpose_tile(src, g_wt + (size_t)z * CC * HH, CC, HH);
}

__global__ void transpose_v_kernel()
{
    const int b = blockIdx.z;
    transpose_tile(g_v + (size_t)b * TT * HH, g_vt + (size_t)b * HH * TT, TT, HH);
}

// ---------------------------------------------------------------------------
// Causal row softmax (in place on g_s), tf32-rounded probs
// ---------------------------------------------------------------------------
__global__ __launch_bounds__(256) void softmax_kernel()
{
    const int row = blockIdx.x;
    const int b = row / TT, i = row % TT;
    float* S = g_s + (size_t)b * TT * TT + (size_t)i * TT;
    const int n = i + 1;
    const int tid = threadIdx.x;

    float vals[8];
    #pragma unroll
    for (int ii = 0; ii < 8; ii++) {
        int j = tid + ii * 256;
        vals[ii] = (j < n) ? S[j] : -CUDART_INF_F;
    }

    __shared__ float red[256];
    float m = vals[0];
    #pragma unroll
    for (int ii = 1; ii < 8; ii++) m = fmaxf(m, vals[ii]);
    red[tid] = m;
    __syncthreads();
    #pragma unroll
    for (int s = 128; s > 0; s >>= 1) {
        if (tid < s) red[tid] = fmaxf(red[tid], red[tid + s]);
        __syncthreads();
    }
    m = red[0];
    __syncthreads();

    float e[8];
    float sum = 0.0f;
    #pragma unroll
    for (int ii = 0; ii < 8; ii++) {
        e[ii] = (vals[ii] == -CUDART_INF_F) ? 0.0f : __expf(vals[ii] - m);
        sum += e[ii];
    }
    red[tid] = sum;
    __syncthreads();
    #pragma unroll
    for (int s = 128; s > 0; s >>= 1) {
        if (tid < s) red[tid] += red[tid + s];
        __syncthreads();
    }
    const float inv = 1.0f / red[0];
    __syncthreads();

    #pragma unroll
    for (int ii = 0; ii < 8; ii++) {
        int j = tid + ii * 256;
        S[j] = rn_tf32(e[ii] * inv);
    }
}

// ---------------------------------------------------------------------------
// Launch
// ---------------------------------------------------------------------------
extern "C" void kernel_launch(void* const* d_in, const int* in_sizes, int n_in,
                              void* d_out, int out_size)
{
    const float* x  = (const float*)d_in[0];
    const float* Wq = (const float*)d_in[1];
    const float* bq = (const float*)d_in[2];
    const float* Wk = (const float*)d_in[3];
    const float* bk = (const float*)d_in[4];
    const float* Wv = (const float*)d_in[5];
    const float* bv = (const float*)d_in[6];
    float* out = (float*)d_out;

    cudaFuncSetAttribute(qkv_mma, cudaFuncAttributeMaxDynamicSharedMemorySize, SMEM_BYTES);
    cudaFuncSetAttribute(scores_mma, cudaFuncAttributeMaxDynamicSharedMemorySize, SMEM_BYTES);
    cudaFuncSetAttribute(pv_mma, cudaFuncAttributeMaxDynamicSharedMemorySize, SMEM_BYTES);

    round_x_kernel<<<MTOT * CC / (256 * 4), 256>>>(x);
    transpose_w_kernel<<<dim3(HH / 32, CC / 32, 3), dim3(32, 8)>>>(Wq, Wk, Wv);
    qkv_mma<<<dim3(HH / TN, MTOT / TM, 3), 256, SMEM_BYTES>>>(bq, bk, bv);
    transpose_v_kernel<<<dim3(HH / 32, TT / 32, BB), dim3(32, 8)>>>();
    scores_mma<<<dim3(TT / TN, TT / TM, BB), 256, SMEM_BYTES>>>();
    softmax_kernel<<<dim3(BB * TT), 256>>>();
    pv_mma<<<dim3(HH / TN, TT / TM, BB), 256, SMEM_BYTES>>>(out);
}

// round 4
// speedup vs baseline: 3.8371x; 1.1371x over previous
#include <cuda_runtime.h>
#include <math_constants.h>
#include <cstdint>

// ---------------------------------------------------------------------------
// Problem constants
// ---------------------------------------------------------------------------
#define BB 4
#define TT 2048
#define CC 768
#define HH 768
#define MTOT (BB * TT)           // 8192
static const float QK_SCALE = 0.03608439182435161f;  // 1/sqrt(768)

// ---------------------------------------------------------------------------
// Scratch globals
// ---------------------------------------------------------------------------
__device__ float g_x [(size_t)MTOT * CC];      // tf32-rounded x
__device__ float g_wt[(size_t)3 * CC * HH];    // W^T, tf32-rounded  [z][n][k]
__device__ float g_q [(size_t)MTOT * HH];      // tf32-rounded
__device__ float g_k [(size_t)MTOT * HH];      // tf32-rounded
__device__ float g_v [(size_t)MTOT * HH];
__device__ float g_vt[(size_t)BB * HH * TT];   // V^T per batch, tf32-rounded
__device__ float g_s [(size_t)BB * TT * TT];   // scores -> probs (tf32-rounded)

// ---------------------------------------------------------------------------
// GEMM config: CTA 128x128, 256 threads (8 warps 2x4), warp tile 64x32,
// K-chunk 32, 3-stage cp.async pipeline.
// Smem: stride 32 floats/row with XOR swizzle (col*4 ^ (row&7)*16).
// All rows a thread reads are == g (mod 8), so the XOR is a per-thread
// constant and fragment LDS is bank-conflict-free.
// 3 stages * 32KB = 96KB -> 2 CTAs/SM.
// ---------------------------------------------------------------------------
#define TM 128
#define TN 128
#define TK 32
#define STAGE_BYTES (2 * 128 * 128)       // A(16KB) + B(16KB)
#define NSTAGE 3
#define SMEM_BYTES (NSTAGE * STAGE_BYTES) // 98304

__device__ __forceinline__ uint32_t smem_u32(const void* p) {
    uint32_t a;
    asm("{ .reg .u64 t; cvta.to.shared.u64 t, %1; cvt.u32.u64 %0, t; }"
        : "=r"(a) : "l"(p));
    return a;
}

__device__ __forceinline__ float rn_tf32(float x) {
    uint32_t u;
    asm("cvt.rn.tf32.f32 %0, %1;" : "=r"(u) : "f"(x));
    return __uint_as_float(u);
}

__device__ __forceinline__ void cp16(uint32_t dst, const void* src) {
    asm volatile("cp.async.cg.shared.global [%0], [%1], 16;"
                 :: "r"(dst), "l"(src) : "memory");
}

__device__ __forceinline__ void mma_tf32(float c[4], const uint32_t a[4],
                                         const uint32_t b[2]) {
    asm volatile(
        "mma.sync.aligned.m16n8k8.row.col.f32.tf32.tf32.f32 "
        "{%0,%1,%2,%3}, {%4,%5,%6,%7}, {%8,%9}, {%0,%1,%2,%3};"
        : "+f"(c[0]), "+f"(c[1]), "+f"(c[2]), "+f"(c[3])
        : "r"(a[0]), "r"(a[1]), "r"(a[2]), "r"(a[3]), "r"(b[0]), "r"(b[1]));
}

// Load one K-chunk (A: 128x32, B: 128x32) into a stage via cp.async,
// applying the XOR swizzle per 16B granule.
__device__ __forceinline__ void load_chunk(uint32_t sA, uint32_t sB,
                                           const float* Ag, int lda,
                                           const float* Bg, int ldb, int tid) {
    #pragma unroll
    for (int i = 0; i < 4; i++) {
        int idx = tid + i * 256;          // 0..1023
        int row = idx >> 3, gc = idx & 7; // 8 x 16B granules per row
        uint32_t off = (uint32_t)(row * 128 + ((gc * 16) ^ ((row & 7) * 16)));
        cp16(sA + off, Ag + (size_t)row * lda + gc * 4);
        cp16(sB + off, Bg + (size_t)row * ldb + gc * 4);
    }
}

// ---------------------------------------------------------------------------
// Generic 128x128 tf32 mma.sync GEMM tile:
//   C[row0+i, col0+j] = scale * sum_k A[row0+i,k] * B[col0+j,k] (+ bias[col])
// A, B data must already be tf32-rounded.
// ---------------------------------------------------------------------------
__device__ __forceinline__ void gemm_tile(
    const float* __restrict__ A, int lda,
    const float* __restrict__ B, int ldb,
    float* __restrict__ C, int ldc,
    int row0, int col0, int K,
    const float* __restrict__ bias, float scale, bool round_out)
{
    extern __shared__ float smf[];
    const uint32_t sbase = smem_u32(smf);

    const int tid   = threadIdx.x;
    const int warp  = tid >> 5;
    const int lane  = tid & 31;
    const int wm    = (warp & 1) * 64;   // warp m offset
    const int wn    = (warp >> 1) * 32;  // warp n offset
    const int g     = lane >> 2;         // group id 0..7
    const int t     = lane & 3;          // thread-in-group 0..3

    const float* Arow = A + (size_t)row0 * lda;
    const float* Brow = B + (size_t)col0 * ldb;
    const int NC = K / TK;

    float acc[4][4][4];
    #pragma unroll
    for (int mi = 0; mi < 4; mi++)
        #pragma unroll
        for (int ni = 0; ni < 4; ni++)
            #pragma unroll
            for (int j = 0; j < 4; j++) acc[mi][ni][j] = 0.0f;

    uint32_t stA[NSTAGE], stB[NSTAGE];
    #pragma unroll
    for (int s = 0; s < NSTAGE; s++) {
        stA[s] = sbase + (uint32_t)(s * STAGE_BYTES);
        stB[s] = stA[s] + (uint32_t)(128 * 128);
    }

    // Prologue: issue loads for first NSTAGE-1 chunks
    #pragma unroll
    for (int s = 0; s < NSTAGE - 1; s++) {
        if (s < NC)
            load_chunk(stA[s], stB[s], Arow + s * TK, lda, Brow + s * TK, ldb, tid);
        asm volatile("cp.async.commit_group;" ::: "memory");
    }

    #pragma unroll 1
    for (int c = 0; c < NC; c++) {
        asm volatile("cp.async.wait_group %0;" :: "n"(NSTAGE - 2) : "memory");
        __syncthreads();

        // Issue next load immediately (stage was fully consumed before the
        // sync above), overlapping with this chunk's compute.
        const int cn = c + NSTAGE - 1;
        if (cn < NC)
            load_chunk(stA[cn % NSTAGE], stB[cn % NSTAGE],
                       Arow + cn * TK, lda, Brow + cn * TK, ldb, tid);
        asm volatile("cp.async.commit_group;" ::: "memory");

        const int s = c % NSTAGE;
        const float* As = smf + (size_t)(stA[s] - sbase) / 4;
        const float* Bs = smf + (size_t)(stB[s] - sbase) / 4;
        // Per-thread constant XOR base: all rows read are == g (mod 8)
        const float* ab = As + (wm + g) * 32 + t;
        const float* bb = Bs + (wn + g) * 32 + t;

        #pragma unroll
        for (int ks = 0; ks < 4; ks++) {
            const int x0 = 4 * ((2 * ks) ^ g);       // cols k0..k0+3 swizzled
            const int x1 = 4 * ((2 * ks + 1) ^ g);   // cols k0+4..k0+7 swizzled
            uint32_t a[4][4], b[4][2];
            #pragma unroll
            for (int mi = 0; mi < 4; mi++) {
                const float* p = ab + mi * (16 * 32);
                a[mi][0] = __float_as_uint(p[x0]);
                a[mi][1] = __float_as_uint(p[8 * 32 + x0]);
                a[mi][2] = __float_as_uint(p[x1]);
                a[mi][3] = __float_as_uint(p[8 * 32 + x1]);
            }
            #pragma unroll
            for (int ni = 0; ni < 4; ni++) {
                const float* p = bb + ni * (8 * 32);
                b[ni][0] = __float_as_uint(p[x0]);
                b[ni][1] = __float_as_uint(p[x1]);
            }
            #pragma unroll
            for (int mi = 0; mi < 4; mi++)
                #pragma unroll
                for (int ni = 0; ni < 4; ni++)
                    mma_tf32(acc[mi][ni], a[mi], b[ni]);
        }
    }

    // Epilogue
    #pragma unroll
    for (int mi = 0; mi < 4; mi++) {
        const int r0 = row0 + wm + mi * 16 + g;
        #pragma unroll
        for (int ni = 0; ni < 4; ni++) {
            const int ccol = col0 + wn + ni * 8 + 2 * t;
            float v0 = acc[mi][ni][0] * scale;
            float v1 = acc[mi][ni][1] * scale;
            float v2 = acc[mi][ni][2] * scale;
            float v3 = acc[mi][ni][3] * scale;
            if (bias) {
                float b0 = bias[ccol], b1 = bias[ccol + 1];
                v0 += b0; v1 += b1; v2 += b0; v3 += b1;
            }
            if (round_out) {
                v0 = rn_tf32(v0); v1 = rn_tf32(v1);
                v2 = rn_tf32(v2); v3 = rn_tf32(v3);
            }
            *(float2*)(C + (size_t)r0 * ldc + ccol) = make_float2(v0, v1);
            *(float2*)(C + (size_t)(r0 + 8) * ldc + ccol) = make_float2(v2, v3);
        }
    }
}

// ---------------------------------------------------------------------------
// GEMM wrappers
// ---------------------------------------------------------------------------
__global__ __launch_bounds__(256, 2) void qkv_mma(
    const float* __restrict__ bq, const float* __restrict__ bk,
    const float* __restrict__ bv)
{
    const int z = blockIdx.z;
    const float* bias = (z == 0) ? bq : (z == 1) ? bk : bv;
    float* out = (z == 0) ? g_q : (z == 1) ? g_k : g_v;
    const float* B = g_wt + (size_t)z * CC * HH;
    gemm_tile(g_x, CC, B, CC, out, HH,
              blockIdx.y * TM, blockIdx.x * TN, CC, bias, 1.0f, true);
}

__global__ __launch_bounds__(256, 2) void scores_mma()
{
    const int nj = blockIdx.x, mi = blockIdx.y, b = blockIdx.z;
    if (nj > mi) return;   // tile fully above diagonal
    const float* q = g_q + (size_t)b * TT * HH;
    const float* k = g_k + (size_t)b * TT * HH;
    gemm_tile(q, HH, k, HH, g_s + (size_t)b * TT * TT, TT,
              mi * TM, nj * TN, HH, nullptr, QK_SCALE, false);
}

__global__ __launch_bounds__(256, 2) void pv_mma(float* __restrict__ out)
{
    const int nj = blockIdx.x, mi = blockIdx.y, b = blockIdx.z;
    const float* P = g_s + (size_t)b * TT * TT;
    const float* Vt = g_vt + (size_t)b * HH * TT;
    gemm_tile(P, TT, Vt, TT, out + (size_t)b * TT * HH, HH,
              mi * TM, nj * TN, (mi + 1) * TM, nullptr, 1.0f, false);
}

// ---------------------------------------------------------------------------
// Elementwise tf32 rounding of x
// ---------------------------------------------------------------------------
__global__ __launch_bounds__(256) void round_x_kernel(const float* __restrict__ x)
{
    size_t i = (size_t)blockIdx.x * 256 + threadIdx.x;
    float4 v = ((const float4*)x)[i];
    v.x = rn_tf32(v.x); v.y = rn_tf32(v.y);
    v.z = rn_tf32(v.z); v.w = rn_tf32(v.w);
    ((float4*)g_x)[i] = v;
}

// ---------------------------------------------------------------------------
// Tiled transpose with tf32 rounding: dst[c][r] = rn(src[r][c])
// ---------------------------------------------------------------------------
__device__ __forceinline__ void transpose_tile(const float* __restrict__ src,
                                               float* __restrict__ dst,
                                               int R, int C)
{
    __shared__ float t[32][33];
    const int c0 = blockIdx.x * 32, r0 = blockIdx.y * 32;
    const int tx = threadIdx.x, ty = threadIdx.y;  // 32 x 8
    #pragma unroll
    for (int i = 0; i < 4; i++)
        t[ty + 8 * i][tx] = src[(size_t)(r0 + ty + 8 * i) * C + c0 + tx];
    __syncthreads();
    #pragma unroll
    for (int i = 0; i < 4; i++)
        dst[(size_t)(c0 + ty + 8 * i) * R + r0 + tx] = rn_tf32(t[tx][ty + 8 * i]);
}

__global__ void transpose_w_kernel(const float* __restrict__ Wq,
                                   const float* __restrict__ Wk,
                                   const float* __restrict__ Wv)
{
    const int z = blockIdx.z;
    const float* src = (z == 0) ? Wq : (z == 1) ? Wk : Wv;
    transpose_tile(src, g_wt + (size_t)z * CC * HH, CC, HH);
}

__global__ void transpose_v_kernel()
{
    const int b = blockIdx.z;
    transpose_tile(g_v + (size_t)b * TT * HH, g_vt + (size_t)b * HH * TT, TT, HH);
}

// ---------------------------------------------------------------------------
// Causal row softmax (in place on g_s), tf32-rounded probs
// ---------------------------------------------------------------------------
__global__ __launch_bounds__(256) void softmax_kernel()
{
    const int row = blockIdx.x;
    const int b = row / TT, i = row % TT;
    float* S = g_s + (size_t)b * TT * TT + (size_t)i * TT;
    const int n = i + 1;
    const int tid = threadIdx.x;

    float vals[8];
    #pragma unroll
    for (int ii = 0; ii < 8; ii++) {
        int j = tid + ii * 256;
        vals[ii] = (j < n) ? S[j] : -CUDART_INF_F;
    }

    __shared__ float red[256];
    float m = vals[0];
    #pragma unroll
    for (int ii = 1; ii < 8; ii++) m = fmaxf(m, vals[ii]);
    red[tid] = m;
    __syncthreads();
    #pragma unroll
    for (int s = 128; s > 0; s >>= 1) {
        if (tid < s) red[tid] = fmaxf(red[tid], red[tid + s]);
        __syncthreads();
    }
    m = red[0];
    __syncthreads();

    float e[8];
    float sum = 0.0f;
    #pragma unroll
    for (int ii = 0; ii < 8; ii++) {
        e[ii] = (vals[ii] == -CUDART_INF_F) ? 0.0f : __expf(vals[ii] - m);
        sum += e[ii];
    }
    red[tid] = sum;
    __syncthreads();
    #pragma unroll
    for (int s = 128; s > 0; s >>= 1) {
        if (tid < s) red[tid] += red[tid + s];
        __syncthreads();
    }
    const float inv = 1.0f / red[0];
    __syncthreads();

    #pragma unroll
    for (int ii = 0; ii < 8; ii++) {
        int j = tid + ii * 256;
        S[j] = rn_tf32(e[ii] * inv);
    }
}

// ---------------------------------------------------------------------------
// Launch
// ---------------------------------------------------------------------------
extern "C" void kernel_launch(void* const* d_in, const int* in_sizes, int n_in,
                              void* d_out, int out_size)
{
    const float* x  = (const float*)d_in[0];
    const float* Wq = (const float*)d_in[1];
    const float* bq = (const float*)d_in[2];
    const float* Wk = (const float*)d_in[3];
    const float* bk = (const float*)d_in[4];
    const float* Wv = (const float*)d_in[5];
    const float* bv = (const float*)d_in[6];
    float* out = (float*)d_out;

    cudaFuncSetAttribute(qkv_mma, cudaFuncAttributeMaxDynamicSharedMemorySize, SMEM_BYTES);
    cudaFuncSetAttribute(scores_mma, cudaFuncAttributeMaxDynamicSharedMemorySize, SMEM_BYTES);
    cudaFuncSetAttribute(pv_mma, cudaFuncAttributeMaxDynamicSharedMemorySize, SMEM_BYTES);

    round_x_kernel<<<MTOT * CC / (256 * 4), 256>>>(x);
    transpose_w_kernel<<<dim3(HH / 32, CC / 32, 3), dim3(32, 8)>>>(Wq, Wk, Wv);
    qkv_mma<<<dim3(HH / TN, MTOT / TM, 3), 256, SMEM_BYTES>>>(bq, bk, bv);
    transpose_v_kernel<<<dim3(HH / 32, TT / 32, BB), dim3(32, 8)>>>();
    scores_mma<<<dim3(TT / TN, TT / TM, BB), 256, SMEM_BYTES>>>();
    softmax_kernel<<<dim3(BB * TT), 256>>>();
    pv_mma<<<dim3(HH / TN, TT / TM, BB), 256, SMEM_BYTES>>>(out);
}

// round 5
// speedup vs baseline: 6.5630x; 1.7104x over previous
#include <cuda_runtime.h>
#include <cuda_fp16.h>
#include <math_constants.h>
#include <cstdint>

// ---------------------------------------------------------------------------
// Problem constants
// ---------------------------------------------------------------------------
#define BB 4
#define TT 2048
#define CC 768
#define HH 768
#define MTOT (BB * TT)           // 8192
static const float QK_SCALE = 0.03608439182435161f;  // 1/sqrt(768)

// ---------------------------------------------------------------------------
// Scratch globals (all operands stored as fp16; scores stay fp32)
// ---------------------------------------------------------------------------
__device__ __half g_x [(size_t)MTOT * CC];
__device__ __half g_wt[(size_t)3 * CC * HH];    // W^T  [z][n][k]
__device__ __half g_q [(size_t)MTOT * HH];
__device__ __half g_k [(size_t)MTOT * HH];
__device__ __half g_v [(size_t)MTOT * HH];
__device__ __half g_vt[(size_t)BB * HH * TT];   // V^T per batch
__device__ float  g_s [(size_t)BB * TT * TT];   // raw scores (fp32!)
__device__ __half g_p [(size_t)BB * TT * TT];   // softmax probs (fp16)

// ---------------------------------------------------------------------------
// GEMM config: CTA 128x128, 256 threads (8 warps 2x4), warp tile 64x32,
// fp16 m16n8k16 mma, K-chunk 64 halfs (128B rows), 3-stage cp.async.
// Smem rows: 64 halfs = 8 x 16B granules, XOR-swizzled by (row&7).
// 3 stages * 32KB = 96KB -> 2 CTAs/SM.
// ---------------------------------------------------------------------------
#define TM 128
#define TN 128
#define TK 64
#define STAGE_BYTES (2 * 128 * 128)       // A(16KB) + B(16KB)
#define NSTAGE 3
#define SMEM_BYTES (NSTAGE * STAGE_BYTES) // 98304

__device__ __forceinline__ uint32_t smem_u32(const void* p) {
    uint32_t a;
    asm("{ .reg .u64 t; cvta.to.shared.u64 t, %1; cvt.u32.u64 %0, t; }"
        : "=r"(a) : "l"(p));
    return a;
}

__device__ __forceinline__ void cp16(uint32_t dst, const void* src) {
    asm volatile("cp.async.cg.shared.global [%0], [%1], 16;"
                 :: "r"(dst), "l"(src) : "memory");
}

__device__ __forceinline__ void mma_f16(float c[4], const uint32_t a[4],
                                        const uint32_t b[2]) {
    asm volatile(
        "mma.sync.aligned.m16n8k16.row.col.f32.f16.f16.f32 "
        "{%0,%1,%2,%3}, {%4,%5,%6,%7}, {%8,%9}, {%0,%1,%2,%3};"
        : "+f"(c[0]), "+f"(c[1]), "+f"(c[2]), "+f"(c[3])
        : "r"(a[0]), "r"(a[1]), "r"(a[2]), "r"(a[3]), "r"(b[0]), "r"(b[1]));
}

// Load one K-chunk (A: 128x64h, B: 128x64h) into a stage via cp.async,
// XOR swizzle per 16B granule (8 halfs).
__device__ __forceinline__ void load_chunk(uint32_t sA, uint32_t sB,
                                           const __half* Ag, int lda,
                                           const __half* Bg, int ldb, int tid) {
    #pragma unroll
    for (int i = 0; i < 4; i++) {
        int idx = tid + i * 256;          // 0..1023
        int row = idx >> 3, gc = idx & 7; // 8 x 16B granules per row
        uint32_t off = (uint32_t)(row * 128 + ((gc * 16) ^ ((row & 7) * 16)));
        cp16(sA + off, Ag + (size_t)row * lda + gc * 8);
        cp16(sB + off, Bg + (size_t)row * ldb + gc * 8);
    }
}

// ---------------------------------------------------------------------------
// Generic 128x128 fp16 mma.sync GEMM tile:
//   C[row0+i, col0+j] = scale * sum_k A[row0+i,k] * B[col0+j,k] (+ bias[col])
// ---------------------------------------------------------------------------
template <bool HALF_OUT>
__device__ __forceinline__ void gemm_tile(
    const __half* __restrict__ A, int lda,
    const __half* __restrict__ B, int ldb,
    void* __restrict__ Cv, int ldc,
    int row0, int col0, int K,
    const float* __restrict__ bias, float scale)
{
    extern __shared__ float smf[];
    const uint32_t sbase = smem_u32(smf);
    const uint32_t* sw = (const uint32_t*)smf;

    const int tid   = threadIdx.x;
    const int warp  = tid >> 5;
    const int lane  = tid & 31;
    const int wm    = (warp & 1) * 64;   // warp m offset
    const int wn    = (warp >> 1) * 32;  // warp n offset
    const int g     = lane >> 2;         // group id 0..7
    const int t     = lane & 3;          // thread-in-group 0..3

    const __half* Arow = A + (size_t)row0 * lda;
    const __half* Brow = B + (size_t)col0 * ldb;
    const int NC = K / TK;

    float acc[4][4][4];
    #pragma unroll
    for (int mi = 0; mi < 4; mi++)
        #pragma unroll
        for (int ni = 0; ni < 4; ni++)
            #pragma unroll
            for (int j = 0; j < 4; j++) acc[mi][ni][j] = 0.0f;

    uint32_t stA[NSTAGE], stB[NSTAGE];
    #pragma unroll
    for (int s = 0; s < NSTAGE; s++) {
        stA[s] = sbase + (uint32_t)(s * STAGE_BYTES);
        stB[s] = stA[s] + (uint32_t)(128 * 128);
    }

    #pragma unroll
    for (int s = 0; s < NSTAGE - 1; s++) {
        if (s < NC)
            load_chunk(stA[s], stB[s], Arow + s * TK, lda, Brow + s * TK, ldb, tid);
        asm volatile("cp.async.commit_group;" ::: "memory");
    }

    #pragma unroll 1
    for (int c = 0; c < NC; c++) {
        asm volatile("cp.async.wait_group %0;" :: "n"(NSTAGE - 2) : "memory");
        __syncthreads();

        const int cn = c + NSTAGE - 1;
        if (cn < NC)
            load_chunk(stA[cn % NSTAGE], stB[cn % NSTAGE],
                       Arow + cn * TK, lda, Brow + cn * TK, ldb, tid);
        asm volatile("cp.async.commit_group;" ::: "memory");

        const int s = c % NSTAGE;
        // word (uint32) views; each smem row = 32 words
        const uint32_t* Aw = sw + (size_t)(stA[s] - sbase) / 4;
        const uint32_t* Bw = sw + (size_t)(stB[s] - sbase) / 4;
        const uint32_t* ab = Aw + (wm + g) * 32 + t;
        const uint32_t* bb = Bw + (wn + g) * 32 + t;

        #pragma unroll
        for (int ks = 0; ks < 4; ks++) {   // k16 steps within the 64-chunk
            const int x0 = 4 * ((2 * ks) ^ g);       // k halves 0..7 (swizzled)
            const int x1 = 4 * ((2 * ks + 1) ^ g);   // k halves 8..15
            uint32_t a[4][4], b[4][2];
            #pragma unroll
            for (int mi = 0; mi < 4; mi++) {
                const uint32_t* p = ab + mi * (16 * 32);
                a[mi][0] = p[x0];
                a[mi][1] = p[8 * 32 + x0];
                a[mi][2] = p[x1];
                a[mi][3] = p[8 * 32 + x1];
            }
            #pragma unroll
            for (int ni = 0; ni < 4; ni++) {
                const uint32_t* p = bb + ni * (8 * 32);
                b[ni][0] = p[x0];
                b[ni][1] = p[x1];
            }
            #pragma unroll
            for (int mi = 0; mi < 4; mi++)
                #pragma unroll
                for (int ni = 0; ni < 4; ni++)
                    mma_f16(acc[mi][ni], a[mi], b[ni]);
        }
    }

    // Epilogue
    #pragma unroll
    for (int mi = 0; mi < 4; mi++) {
        const int r0 = row0 + wm + mi * 16 + g;
        #pragma unroll
        for (int ni = 0; ni < 4; ni++) {
            const int ccol = col0 + wn + ni * 8 + 2 * t;
            float v0 = acc[mi][ni][0] * scale;
            float v1 = acc[mi][ni][1] * scale;
            float v2 = acc[mi][ni][2] * scale;
            float v3 = acc[mi][ni][3] * scale;
            if (bias) {
                float b0 = bias[ccol], b1 = bias[ccol + 1];
                v0 += b0; v1 += b1; v2 += b0; v3 += b1;
            }
            if (HALF_OUT) {
                __half* C = (__half*)Cv;
                *(__half2*)(C + (size_t)r0 * ldc + ccol) = __floats2half2_rn(v0, v1);
                *(__half2*)(C + (size_t)(r0 + 8) * ldc + ccol) = __floats2half2_rn(v2, v3);
            } else {
                float* C = (float*)Cv;
                *(float2*)(C + (size_t)r0 * ldc + ccol) = make_float2(v0, v1);
                *(float2*)(C + (size_t)(r0 + 8) * ldc + ccol) = make_float2(v2, v3);
            }
        }
    }
}

// ---------------------------------------------------------------------------
// GEMM wrappers
// ---------------------------------------------------------------------------
__global__ __launch_bounds__(256, 2) void qkv_mma(
    const float* __restrict__ bq, const float* __restrict__ bk,
    const float* __restrict__ bv)
{
    const int z = blockIdx.z;
    const float* bias = (z == 0) ? bq : (z == 1) ? bk : bv;
    __half* out = (z == 0) ? g_q : (z == 1) ? g_k : g_v;
    const __half* B = g_wt + (size_t)z * CC * HH;
    gemm_tile<true>(g_x, CC, B, CC, out, HH,
                    blockIdx.y * TM, blockIdx.x * TN, CC, bias, 1.0f);
}

__global__ __launch_bounds__(256, 2) void scores_mma()
{
    const int nj = blockIdx.x, mi = blockIdx.y, b = blockIdx.z;
    if (nj > mi) return;   // tile fully above diagonal
    const __half* q = g_q + (size_t)b * TT * HH;
    const __half* k = g_k + (size_t)b * TT * HH;
    gemm_tile<false>(q, HH, k, HH, g_s + (size_t)b * TT * TT, TT,
                     mi * TM, nj * TN, HH, nullptr, QK_SCALE);
}

__global__ __launch_bounds__(256, 2) void pv_mma(float* __restrict__ out)
{
    const int nj = blockIdx.x, mi = blockIdx.y, b = blockIdx.z;
    const __half* P = g_p + (size_t)b * TT * TT;
    const __half* Vt = g_vt + (size_t)b * HH * TT;
    gemm_tile<false>(P, TT, Vt, TT, out + (size_t)b * TT * HH, HH,
                     mi * TM, nj * TN, (mi + 1) * TM, nullptr, 1.0f);
}

// ---------------------------------------------------------------------------
// Convert x to fp16 (8 elements/thread)
// ---------------------------------------------------------------------------
__global__ __launch_bounds__(256) void conv_x_kernel(const float* __restrict__ x)
{
    size_t i = (size_t)blockIdx.x * 256 + threadIdx.x;
    const float4* p = (const float4*)x + 2 * i;
    float4 v0 = p[0], v1 = p[1];
    __half2 h[4];
    h[0] = __floats2half2_rn(v0.x, v0.y);
    h[1] = __floats2half2_rn(v0.z, v0.w);
    h[2] = __floats2half2_rn(v1.x, v1.y);
    h[3] = __floats2half2_rn(v1.z, v1.w);
    ((uint4*)g_x)[i] = *(uint4*)h;
}

// ---------------------------------------------------------------------------
// Transposes (to fp16)
// ---------------------------------------------------------------------------
__global__ void transpose_w_kernel(const float* __restrict__ Wq,
                                   const float* __restrict__ Wk,
                                   const float* __restrict__ Wv)
{
    const int z = blockIdx.z;
    const float* src = (z == 0) ? Wq : (z == 1) ? Wk : Wv;
    __half* dst = g_wt + (size_t)z * CC * HH;
    __shared__ float t[32][33];
    const int c0 = blockIdx.x * 32, r0 = blockIdx.y * 32;
    const int tx = threadIdx.x, ty = threadIdx.y;
    #pragma unroll
    for (int i = 0; i < 4; i++)
        t[ty + 8 * i][tx] = src[(size_t)(r0 + ty + 8 * i) * HH + c0 + tx];
    __syncthreads();
    #pragma unroll
    for (int i = 0; i < 4; i++)
        dst[(size_t)(c0 + ty + 8 * i) * CC + r0 + tx] =
            __float2half_rn(t[tx][ty + 8 * i]);
}

__global__ void transpose_v_kernel()
{
    const int b = blockIdx.z;
    const __half* src = g_v + (size_t)b * TT * HH;
    __half* dst = g_vt + (size_t)b * HH * TT;
    __shared__ float t[32][33];
    const int c0 = blockIdx.x * 32, r0 = blockIdx.y * 32;
    const int tx = threadIdx.x, ty = threadIdx.y;
    #pragma unroll
    for (int i = 0; i < 4; i++)
        t[ty + 8 * i][tx] = __half2float(src[(size_t)(r0 + ty + 8 * i) * HH + c0 + tx]);
    __syncthreads();
    #pragma unroll
    for (int i = 0; i < 4; i++)
        dst[(size_t)(c0 + ty + 8 * i) * TT + r0 + tx] =
            __float2half_rn(t[tx][ty + 8 * i]);  // exact (already half-valued)
}

// ---------------------------------------------------------------------------
// Causal row softmax: read fp32 g_s, write fp16 probs to g_p
// Each thread owns 8 contiguous columns.
// ---------------------------------------------------------------------------
__global__ __launch_bounds__(256) void softmax_kernel()
{
    const int row = blockIdx.x;
    const int b = row / TT, i = row % TT;
    const float* S = g_s + (size_t)b * TT * TT + (size_t)i * TT;
    __half* P = g_p + (size_t)b * TT * TT + (size_t)i * TT;
    const int n = i + 1;
    const int tid = threadIdx.x;
    const int base = tid * 8;

    float4 u0 = ((const float4*)S)[tid * 2];
    float4 u1 = ((const float4*)S)[tid * 2 + 1];
    float vals[8] = {u0.x, u0.y, u0.z, u0.w, u1.x, u1.y, u1.z, u1.w};
    #pragma unroll
    for (int jj = 0; jj < 8; jj++)
        if (base + jj >= n) vals[jj] = -CUDART_INF_F;

    __shared__ float red[256];
    float m = vals[0];
    #pragma unroll
    for (int jj = 1; jj < 8; jj++) m = fmaxf(m, vals[jj]);
    red[tid] = m;
    __syncthreads();
    #pragma unroll
    for (int s = 128; s > 0; s >>= 1) {
        if (tid < s) red[tid] = fmaxf(red[tid], red[tid + s]);
        __syncthreads();
    }
    m = red[0];
    __syncthreads();

    float e[8];
    float sum = 0.0f;
    #pragma unroll
    for (int jj = 0; jj < 8; jj++) {
        e[jj] = (vals[jj] == -CUDART_INF_F) ? 0.0f : __expf(vals[jj] - m);
        sum += e[jj];
    }
    red[tid] = sum;
    __syncthreads();
    #pragma unroll
    for (int s = 128; s > 0; s >>= 1) {
        if (tid < s) red[tid] += red[tid + s];
        __syncthreads();
    }
    const float inv = 1.0f / red[0];

    __half2 h[4];
    #pragma unroll
    for (int jj = 0; jj < 4; jj++)
        h[jj] = __floats2half2_rn(e[2 * jj] * inv, e[2 * jj + 1] * inv);
    ((uint4*)P)[tid] = *(uint4*)h;
}

// ---------------------------------------------------------------------------
// Launch
// ---------------------------------------------------------------------------
extern "C" void kernel_launch(void* const* d_in, const int* in_sizes, int n_in,
                              void* d_out, int out_size)
{
    const float* x  = (const float*)d_in[0];
    const float* Wq = (const float*)d_in[1];
    const float* bq = (const float*)d_in[2];
    const float* Wk = (const float*)d_in[3];
    const float* bk = (const float*)d_in[4];
    const float* Wv = (const float*)d_in[5];
    const float* bv = (const float*)d_in[6];
    float* out = (float*)d_out;

    cudaFuncSetAttribute(qkv_mma, cudaFuncAttributeMaxDynamicSharedMemorySize, SMEM_BYTES);
    cudaFuncSetAttribute(scores_mma, cudaFuncAttributeMaxDynamicSharedMemorySize, SMEM_BYTES);
    cudaFuncSetAttribute(pv_mma, cudaFuncAttributeMaxDynamicSharedMemorySize, SMEM_BYTES);

    conv_x_kernel<<<MTOT * CC / (256 * 8), 256>>>(x);
    transpose_w_kernel<<<dim3(HH / 32, CC / 32, 3), dim3(32, 8)>>>(Wq, Wk, Wv);
    qkv_mma<<<dim3(HH / TN, MTOT / TM, 3), 256, SMEM_BYTES>>>(bq, bk, bv);
    transpose_v_kernel<<<dim3(HH / 32, TT / 32, BB), dim3(32, 8)>>>();
    scores_mma<<<dim3(TT / TN, TT / TM, BB), 256, SMEM_BYTES>>>();
    softmax_kernel<<<dim3(BB * TT), 256>>>();
    pv_mma<<<dim3(HH / TN, TT / TM, BB), 256, SMEM_BYTES>>>(out);
}